// round 1
// baseline (speedup 1.0000x reference)
#include <cuda_runtime.h>
#include <cuda_bf16.h>

// WindowAttention fused kernel (fp32 baseline).
// One CTA per window: 16384 CTAs x 256 threads.
// Phases: load x -> QKV gemm (smem tiled) -> per-(head,row) attention with
// register softmax -> proj gemm -> store.

#define DIMC   128
#define NHEAD  4
#define HDIM   32
#define NTOK   64
#define NWIN   4096
#define ST     132   // padded fp32 stride for 128-wide smem rows (bank-conflict avoidance)
#define MST    65    // mask smem stride

// smem layout (floats):
//  qs  [64][ST]
//  ks  [64][ST]
//  vs  [64][ST]
//  xs  [64][ST]   (reused as attention output "ao" after QKV phase)
//  wt  [64][ST]   (weight tile staging, reused for mask? no - separate)
//  biasbf  bf16[4][64][64]  layout [h][m][row]  (32 KB)
//  mask_s  [64][MST]        (16.6 KB)
#define SMEM_FLOATS (5 * 64 * ST)
#define SMEM_BYTES  (SMEM_FLOATS * 4 + NHEAD * NTOK * NTOK * 2 + NTOK * MST * 4)

__global__ __launch_bounds__(256, 1)
void win_attn_kernel(const float* __restrict__ x,
                     const float* __restrict__ mask,
                     const float* __restrict__ qkv_w,
                     const float* __restrict__ qkv_b,
                     const float* __restrict__ proj_w,
                     const float* __restrict__ proj_b,
                     const float* __restrict__ bias_table,
                     const int*   __restrict__ rel_index,
                     float* __restrict__ out)
{
    extern __shared__ float sm[];
    float* qs = sm;
    float* ks = qs + 64 * ST;
    float* vs = ks + 64 * ST;
    float* xs = vs + 64 * ST;           // reused as ao after QKV
    float* wt = xs + 64 * ST;
    __nv_bfloat16* biasbf = (__nv_bfloat16*)(wt + 64 * ST);
    float* mask_s = (float*)(biasbf + NHEAD * NTOK * NTOK);

    const int tid  = threadIdx.x;
    const int b    = blockIdx.x;
    const int widx = b & (NWIN - 1);
    const float qscale = 0.17677669529663687f;  // 32^-0.5

    // ---- Phase 0: load x window, precompute bias (bf16), stage mask ----
    {
        const float4* xg = (const float4*)(x + (size_t)b * NTOK * DIMC);
        #pragma unroll
        for (int i = 0; i < 8; i++) {
            int idx = tid + i * 256;        // float4 index: row = idx/32, c4 = idx%32
            int r = idx >> 5, c4 = idx & 31;
            float4 v = xg[idx];
            *(float4*)&xs[r * ST + c4 * 4] = v;
        }
    }
    {
        // bias layout [h][m][row] so attention LDS is conflict-free across lanes(=rows)
        #pragma unroll 4
        for (int i = 0; i < 64; i++) {
            int idx = tid + i * 256;        // 0..16383
            int h  = idx >> 12;
            int rm = idx & 4095;            // r*64 + m
            int r  = rm >> 6, m = rm & 63;
            int ri = rel_index[rm];
            float bv = bias_table[ri * NHEAD + h];
            biasbf[h * 4096 + m * 64 + r] = __float2bfloat16(bv);
        }
    }
    {
        const float4* mg = (const float4*)(mask + (size_t)widx * NTOK * NTOK);
        #pragma unroll
        for (int i = 0; i < 4; i++) {
            int idx = tid + i * 256;        // float4 idx: row = idx/16, c4 = idx%16
            int r = idx >> 4, c4 = idx & 15;
            float4 v = mg[idx];
            mask_s[r * MST + c4 * 4 + 0] = v.x;
            mask_s[r * MST + c4 * 4 + 1] = v.y;
            mask_s[r * MST + c4 * 4 + 2] = v.z;
            mask_s[r * MST + c4 * 4 + 3] = v.w;
        }
    }
    __syncthreads();

    // ---- Phase 1: QKV gemm. 6 column tiles of 64 over 384 output cols ----
    const int ty = tid >> 4;   // 0..15 -> rows ty*4..+3
    const int tx = tid & 15;   // 0..15 -> cols tx*4..+3
    for (int t = 0; t < 6; t++) {
        // stage weight tile: wt[j][k] = qkv_w[(t*64+j)*128 + k]
        const float4* wg = (const float4*)(qkv_w + (size_t)t * 64 * DIMC);
        #pragma unroll
        for (int i = 0; i < 8; i++) {
            int idx = tid + i * 256;
            int r = idx >> 5, c4 = idx & 31;
            *(float4*)&wt[r * ST + c4 * 4] = wg[idx];
        }
        __syncthreads();

        float acc[4][4];
        #pragma unroll
        for (int i = 0; i < 4; i++)
            #pragma unroll
            for (int j = 0; j < 4; j++) acc[i][j] = 0.f;

        const float* xr = &xs[(ty * 4) * ST];
        const float* wr = &wt[(tx * 4) * ST];
        #pragma unroll 4
        for (int k = 0; k < DIMC; k += 4) {
            float4 a0 = *(const float4*)&xr[0 * ST + k];
            float4 a1 = *(const float4*)&xr[1 * ST + k];
            float4 a2 = *(const float4*)&xr[2 * ST + k];
            float4 a3 = *(const float4*)&xr[3 * ST + k];
            float4 b0 = *(const float4*)&wr[0 * ST + k];
            float4 b1 = *(const float4*)&wr[1 * ST + k];
            float4 b2 = *(const float4*)&wr[2 * ST + k];
            float4 b3 = *(const float4*)&wr[3 * ST + k];
            const float4 A[4] = {a0, a1, a2, a3};
            const float4 B[4] = {b0, b1, b2, b3};
            #pragma unroll
            for (int i = 0; i < 4; i++)
                #pragma unroll
                for (int j = 0; j < 4; j++) {
                    acc[i][j] += A[i].x * B[j].x;
                    acc[i][j] += A[i].y * B[j].y;
                    acc[i][j] += A[i].z * B[j].z;
                    acc[i][j] += A[i].w * B[j].w;
                }
        }

        float* dst; int coff; float sc;
        if (t < 2)      { dst = qs; coff = t * 64;       sc = qscale; }
        else if (t < 4) { dst = ks; coff = (t - 2) * 64; sc = 1.f; }
        else            { dst = vs; coff = (t - 4) * 64; sc = 1.f; }
        #pragma unroll
        for (int i = 0; i < 4; i++)
            #pragma unroll
            for (int j = 0; j < 4; j++) {
                int gc = t * 64 + tx * 4 + j;
                dst[(ty * 4 + i) * ST + coff + tx * 4 + j] =
                    (acc[i][j] + qkv_b[gc]) * sc;
            }
        __syncthreads();
    }

    // ---- Phase 2: attention. thread = (head, row) ----
    {
        const int head = tid >> 6;
        const int row  = tid & 63;

        float4 q4[8];
        const float* qrow = &qs[row * ST + head * HDIM];
        #pragma unroll
        for (int i = 0; i < 8; i++) q4[i] = *(const float4*)&qrow[i * 4];

        float s[64];
        float mx = -1e30f;
        #pragma unroll
        for (int m = 0; m < 64; m++) {
            const float* krow = &ks[m * ST + head * HDIM];
            float acc = 0.f;
            #pragma unroll
            for (int i = 0; i < 8; i++) {
                float4 kk = *(const float4*)&krow[i * 4];   // broadcast across lanes
                acc += q4[i].x * kk.x;
                acc += q4[i].y * kk.y;
                acc += q4[i].z * kk.z;
                acc += q4[i].w * kk.w;
            }
            acc += __bfloat162float(biasbf[head * 4096 + m * 64 + row]);
            acc += mask_s[row * MST + m];
            s[m] = acc;
            mx = fmaxf(mx, acc);
        }
        float sum = 0.f;
        #pragma unroll
        for (int m = 0; m < 64; m++) {
            float p = __expf(s[m] - mx);
            s[m] = p;
            sum += p;
        }
        const float rinv = 1.0f / sum;

        float oacc[HDIM];
        #pragma unroll
        for (int d = 0; d < HDIM; d++) oacc[d] = 0.f;
        #pragma unroll
        for (int m = 0; m < 64; m++) {
            float p = s[m];
            const float* vrow = &vs[m * ST + head * HDIM];
            #pragma unroll
            for (int i = 0; i < 8; i++) {
                float4 vv = *(const float4*)&vrow[i * 4];   // broadcast across lanes
                oacc[i * 4 + 0] += p * vv.x;
                oacc[i * 4 + 1] += p * vv.y;
                oacc[i * 4 + 2] += p * vv.z;
                oacc[i * 4 + 3] += p * vv.w;
            }
        }
        float* aor = &xs[row * ST + head * HDIM];   // ao reuses xs
        #pragma unroll
        for (int d = 0; d < HDIM; d++) aor[d] = oacc[d] * rinv;
    }
    __syncthreads();

    // ---- Phase 3: proj gemm: out = ao @ proj_w^T + proj_b ----
    float* og = out + (size_t)b * NTOK * DIMC;
    for (int ct = 0; ct < 2; ct++) {
        const float4* wg = (const float4*)(proj_w + (size_t)ct * 64 * DIMC);
        #pragma unroll
        for (int i = 0; i < 8; i++) {
            int idx = tid + i * 256;
            int r = idx >> 5, c4 = idx & 31;
            *(float4*)&wt[r * ST + c4 * 4] = wg[idx];
        }
        __syncthreads();

        float acc[4][4];
        #pragma unroll
        for (int i = 0; i < 4; i++)
            #pragma unroll
            for (int j = 0; j < 4; j++) acc[i][j] = 0.f;

        const float* ar = &xs[(ty * 4) * ST];
        const float* wr = &wt[(tx * 4) * ST];
        #pragma unroll 4
        for (int k = 0; k < DIMC; k += 4) {
            float4 a0 = *(const float4*)&ar[0 * ST + k];
            float4 a1 = *(const float4*)&ar[1 * ST + k];
            float4 a2 = *(const float4*)&ar[2 * ST + k];
            float4 a3 = *(const float4*)&ar[3 * ST + k];
            float4 b0 = *(const float4*)&wr[0 * ST + k];
            float4 b1 = *(const float4*)&wr[1 * ST + k];
            float4 b2 = *(const float4*)&wr[2 * ST + k];
            float4 b3 = *(const float4*)&wr[3 * ST + k];
            const float4 A[4] = {a0, a1, a2, a3};
            const float4 B[4] = {b0, b1, b2, b3};
            #pragma unroll
            for (int i = 0; i < 4; i++)
                #pragma unroll
                for (int j = 0; j < 4; j++) {
                    acc[i][j] += A[i].x * B[j].x;
                    acc[i][j] += A[i].y * B[j].y;
                    acc[i][j] += A[i].z * B[j].z;
                    acc[i][j] += A[i].w * B[j].w;
                }
        }

        int c0 = ct * 64 + tx * 4;
        float b0 = proj_b[c0 + 0];
        float b1 = proj_b[c0 + 1];
        float b2 = proj_b[c0 + 2];
        float b3 = proj_b[c0 + 3];
        #pragma unroll
        for (int i = 0; i < 4; i++) {
            float4 v;
            v.x = acc[i][0] + b0;
            v.y = acc[i][1] + b1;
            v.z = acc[i][2] + b2;
            v.w = acc[i][3] + b3;
            *(float4*)&og[(ty * 4 + i) * DIMC + c0] = v;
        }
        __syncthreads();
    }
}

extern "C" void kernel_launch(void* const* d_in, const int* in_sizes, int n_in,
                              void* d_out, int out_size) {
    const float* x          = (const float*)d_in[0];
    const float* mask       = (const float*)d_in[1];
    const float* qkv_w      = (const float*)d_in[2];
    const float* qkv_b      = (const float*)d_in[3];
    const float* proj_w     = (const float*)d_in[4];
    const float* proj_b     = (const float*)d_in[5];
    const float* bias_table = (const float*)d_in[6];
    const int*   rel_index  = (const int*)d_in[7];
    float* out = (float*)d_out;

    cudaFuncSetAttribute(win_attn_kernel,
                         cudaFuncAttributeMaxDynamicSharedMemorySize, SMEM_BYTES);
    win_attn_kernel<<<16384, 256, SMEM_BYTES>>>(
        x, mask, qkv_w, qkv_b, proj_w, proj_b, bias_table, rel_index, out);
}

// round 2
// speedup vs baseline: 2.2757x; 2.2757x over previous
#include <cuda_runtime.h>
#include <cuda_bf16.h>

#define DIMC   128
#define NHEAD  4
#define NTOK   64
#define NWIN   4096
#define ST     132   // Q/K/V/x smem row stride (floats)
#define BST    388   // weight-chunk smem row stride (floats)
#define MST    65    // mask smem row stride

typedef unsigned long long ull;

__device__ __forceinline__ void ffma2(ull& d, ull a, ull b) {
    asm("fma.rn.f32x2 %0, %1, %2, %0;" : "+l"(d) : "l"(a), "l"(b));
}
__device__ __forceinline__ ull addf2(ull a, ull b) {
    ull r; asm("add.rn.f32x2 %0, %1, %2;" : "=l"(r) : "l"(a), "l"(b)); return r;
}
__device__ __forceinline__ ull pack2(float x, float y) {
    ull r; asm("mov.b64 %0, {%1, %2};" : "=l"(r) : "f"(x), "f"(y)); return r;
}
__device__ __forceinline__ float2 unpk(ull u) {
    float2 r; asm("mov.b64 {%0, %1}, %2;" : "=f"(r.x), "=f"(r.y) : "l"(u)); return r;
}

union F4U { float4 f; ull u[2]; };

// Precomputed relative-position bias, layout [h][m][row], bf16.
__device__ __nv_bfloat16 g_bias[NHEAD * NTOK * NTOK];

__global__ void bias_prep_kernel(const float* __restrict__ bias_table,
                                 const int*   __restrict__ rel_index) {
    int idx = blockIdx.x * 256 + threadIdx.x;      // 0..16383
    int h  = idx >> 12;
    int rm = idx & 4095;                           // r*64 + m
    int r  = rm >> 6, m = rm & 63;
    g_bias[h * 4096 + m * 64 + r] =
        __float2bfloat16(bias_table[rel_index[rm] * NHEAD + h]);
}

// smem float offsets
#define OFF_QS   0
#define OFF_KS   8448
#define OFF_VS   16896
#define OFF_XS   25344
#define OFF_BT   33792
#define OFF_SB   40000   // 512 floats: qkv_b(384) + proj_b(128)
#define OFF_MASK 40512   // 64*65
#define FLOATS_TOTAL 44672
#define SMEM_BYTES (FLOATS_TOTAL * 4 + NHEAD * NTOK * NTOK * 2)

__global__ __launch_bounds__(256, 1)
void win_attn_kernel(const float* __restrict__ x,
                     const float* __restrict__ mask,
                     const float* __restrict__ qkv_w,
                     const float* __restrict__ qkv_b,
                     const float* __restrict__ proj_w,
                     const float* __restrict__ proj_b,
                     float* __restrict__ out)
{
    extern __shared__ float sm[];
    float* qs     = sm + OFF_QS;
    float* ks     = sm + OFF_KS;
    float* vs     = sm + OFF_VS;
    float* xs     = sm + OFF_XS;   // x, later reused as attention output
    float* bt     = sm + OFF_BT;   // weight K-chunk [16][BST]
    float* sbias  = sm + OFF_SB;
    float* mask_s = sm + OFF_MASK;
    __nv_bfloat16* biasbf = (__nv_bfloat16*)(sm + FLOATS_TOTAL);

    const int tid  = threadIdx.x;
    const int b    = blockIdx.x;
    const int widx = b & (NWIN - 1);
    const float qscale = 0.17677669529663687f;  // 32^-0.5

    // ---- Phase 0: stage x, mask, biases, bias table ----
    {
        const float4* xg = (const float4*)(x + (size_t)b * NTOK * DIMC);
        #pragma unroll
        for (int i = 0; i < 8; i++) {
            int idx = tid + i * 256;
            int r = idx >> 5, c4 = idx & 31;
            *(float4*)&xs[r * ST + c4 * 4] = xg[idx];
        }
    }
    {
        const float4* mg = (const float4*)(mask + (size_t)widx * NTOK * NTOK);
        #pragma unroll
        for (int i = 0; i < 4; i++) {
            int idx = tid + i * 256;
            int r = idx >> 4, c4 = idx & 15;
            float4 v = mg[idx];
            mask_s[r * MST + c4 * 4 + 0] = v.x;
            mask_s[r * MST + c4 * 4 + 1] = v.y;
            mask_s[r * MST + c4 * 4 + 2] = v.z;
            mask_s[r * MST + c4 * 4 + 3] = v.w;
        }
    }
    {
        sbias[tid] = qkv_b[tid & 255] * 0.f + qkv_b[tid];  // tid<256 -> qkv_b[tid]
        int t2 = 256 + tid;
        sbias[t2] = (t2 < 384) ? qkv_b[t2] : proj_b[t2 - 384];
    }
    {
        const uint4* gb = (const uint4*)g_bias;
        uint4* sb4 = (uint4*)biasbf;
        #pragma unroll
        for (int i = 0; i < 8; i++) sb4[tid + i * 256] = gb[tid + i * 256];
    }

    // ---- Phase 1: QKV gemm (64x384x128), K-chunked, f32x2 packed ----
    const int ty = tid >> 5;   // 0..7  -> rows ty*8..+7
    const int tx = tid & 31;   // 0..31 -> cols tx*12..+11 (6 pairs)
    {
        ull acc[8][6];
        #pragma unroll
        for (int i = 0; i < 8; i++)
            #pragma unroll
            for (int j = 0; j < 6; j++) acc[i][j] = 0ULL;

        const float4* wq4 = (const float4*)qkv_w;  // [384][32] float4
        for (int kb = 0; kb < 8; kb++) {
            __syncthreads();   // previous chunk compute done before overwrite
            // stage bt[k][col] = qkv_w[col][kb*16+k], k=0..15, col=0..383
            #pragma unroll
            for (int i = 0; i < 6; i++) {
                int idx = tid + i * 256;            // 0..1535
                int col = idx >> 2, k4 = idx & 3;
                float4 g = wq4[col * 32 + kb * 4 + k4];
                int base = (k4 * 4) * BST + col;
                bt[base]           = g.x;
                bt[base + BST]     = g.y;
                bt[base + 2 * BST] = g.z;
                bt[base + 3 * BST] = g.w;
            }
            __syncthreads();

            #pragma unroll
            for (int k4 = 0; k4 < 4; k4++) {
                float4 a4[8];
                #pragma unroll
                for (int i = 0; i < 8; i++)
                    a4[i] = *(const float4*)&xs[(ty * 8 + i) * ST + kb * 16 + k4 * 4];
                #pragma unroll
                for (int kk = 0; kk < 4; kk++) {
                    ull ap[8];
                    #pragma unroll
                    for (int i = 0; i < 8; i++) {
                        float av = ((const float*)&a4[i])[kk];
                        ap[i] = pack2(av, av);
                    }
                    const float* brow = &bt[(k4 * 4 + kk) * BST + tx * 12];
                    F4U b0, b1, b2;
                    b0.f = *(const float4*)&brow[0];
                    b1.f = *(const float4*)&brow[4];
                    b2.f = *(const float4*)&brow[8];
                    const ull bp[6] = {b0.u[0], b0.u[1], b1.u[0], b1.u[1], b2.u[0], b2.u[1]};
                    #pragma unroll
                    for (int i = 0; i < 8; i++)
                        #pragma unroll
                        for (int j = 0; j < 6; j++)
                            ffma2(acc[i][j], ap[i], bp[j]);
                }
            }
        }

        // write Q (scaled) / K / V
        #pragma unroll
        for (int i = 0; i < 8; i++) {
            int r = ty * 8 + i;
            #pragma unroll
            for (int jp = 0; jp < 6; jp++) {
                float2 v = unpk(acc[i][jp]);
                int c0 = tx * 12 + jp * 2;
                #pragma unroll
                for (int e = 0; e < 2; e++) {
                    int c = c0 + e;
                    float val = (e ? v.y : v.x) + sbias[c];
                    if (c < 128)      qs[r * ST + c]       = val * qscale;
                    else if (c < 256) ks[r * ST + (c - 128)] = val;
                    else              vs[r * ST + (c - 256)] = val;
                }
            }
        }
    }
    __syncthreads();

    // ---- Phase 2: attention, thread = (head,row) ----
    {
        const int head = tid >> 6;
        const int row  = tid & 63;

        F4U q4[8];
        const float* qrow = &qs[row * ST + head * 32];
        #pragma unroll
        for (int i = 0; i < 8; i++) q4[i].f = *(const float4*)&qrow[i * 4];

        float s[64];
        float mx = -1e30f;
        #pragma unroll
        for (int m = 0; m < 64; m++) {
            const float* krow = &ks[m * ST + head * 32];
            ull a0 = 0ULL, a1 = 0ULL, a2 = 0ULL, a3 = 0ULL;
            #pragma unroll
            for (int i = 0; i < 8; i += 2) {
                F4U kv0, kv1;
                kv0.f = *(const float4*)&krow[i * 4];
                kv1.f = *(const float4*)&krow[i * 4 + 4];
                ffma2(a0, q4[i].u[0],     kv0.u[0]);
                ffma2(a1, q4[i].u[1],     kv0.u[1]);
                ffma2(a2, q4[i + 1].u[0], kv1.u[0]);
                ffma2(a3, q4[i + 1].u[1], kv1.u[1]);
            }
            float2 t = unpk(addf2(addf2(a0, a1), addf2(a2, a3)));
            float acc = t.x + t.y;
            acc += __bfloat162float(biasbf[head * 4096 + m * 64 + row]);
            acc += mask_s[row * MST + m];
            s[m] = acc;
            mx = fmaxf(mx, acc);
        }
        float sum = 0.f;
        #pragma unroll
        for (int m = 0; m < 64; m++) {
            float p = __expf(s[m] - mx);
            s[m] = p;
            sum += p;
        }
        const float rinv = 1.0f / sum;

        ull o[16];
        #pragma unroll
        for (int j = 0; j < 16; j++) o[j] = 0ULL;
        #pragma unroll
        for (int m = 0; m < 64; m++) {
            ull pp = pack2(s[m], s[m]);
            const float* vrow = &vs[m * ST + head * 32];
            #pragma unroll
            for (int i = 0; i < 8; i++) {
                F4U vv; vv.f = *(const float4*)&vrow[i * 4];
                ffma2(o[i * 2],     pp, vv.u[0]);
                ffma2(o[i * 2 + 1], pp, vv.u[1]);
            }
        }
        float* aor = &xs[row * ST + head * 32];
        #pragma unroll
        for (int j = 0; j < 16; j++) {
            float2 v = unpk(o[j]);
            aor[j * 2]     = v.x * rinv;
            aor[j * 2 + 1] = v.y * rinv;
        }
    }

    // ---- Phase 3: proj gemm (64x128x128), K-chunked, f32x2 ----
    {
        ull pacc[8][2];
        #pragma unroll
        for (int i = 0; i < 8; i++) { pacc[i][0] = 0ULL; pacc[i][1] = 0ULL; }

        const float4* wp4 = (const float4*)proj_w;   // [128][32] float4
        for (int kb = 0; kb < 8; kb++) {
            __syncthreads();
            #pragma unroll
            for (int i = 0; i < 2; i++) {
                int idx = tid + i * 256;             // 0..511
                int col = idx >> 2, k4 = idx & 3;
                float4 g = wp4[col * 32 + kb * 4 + k4];
                int base = (k4 * 4) * BST + col;
                bt[base]           = g.x;
                bt[base + BST]     = g.y;
                bt[base + 2 * BST] = g.z;
                bt[base + 3 * BST] = g.w;
            }
            __syncthreads();

            #pragma unroll
            for (int k4 = 0; k4 < 4; k4++) {
                float4 a4[8];
                #pragma unroll
                for (int i = 0; i < 8; i++)
                    a4[i] = *(const float4*)&xs[(ty * 8 + i) * ST + kb * 16 + k4 * 4];
                #pragma unroll
                for (int kk = 0; kk < 4; kk++) {
                    const float* brow = &bt[(k4 * 4 + kk) * BST + tx * 4];
                    F4U bv; bv.f = *(const float4*)&brow[0];
                    #pragma unroll
                    for (int i = 0; i < 8; i++) {
                        float av = ((const float*)&a4[i])[kk];
                        ull ap = pack2(av, av);
                        ffma2(pacc[i][0], ap, bv.u[0]);
                        ffma2(pacc[i][1], ap, bv.u[1]);
                    }
                }
            }
        }

        float* og = out + (size_t)b * NTOK * DIMC;
        int c0 = tx * 4;
        float pb0 = sbias[384 + c0];
        float pb1 = sbias[384 + c0 + 1];
        float pb2 = sbias[384 + c0 + 2];
        float pb3 = sbias[384 + c0 + 3];
        #pragma unroll
        for (int i = 0; i < 8; i++) {
            float2 v0 = unpk(pacc[i][0]);
            float2 v1 = unpk(pacc[i][1]);
            float4 o;
            o.x = v0.x + pb0; o.y = v0.y + pb1;
            o.z = v1.x + pb2; o.w = v1.y + pb3;
            *(float4*)&og[(ty * 8 + i) * DIMC + c0] = o;
        }
    }
}

extern "C" void kernel_launch(void* const* d_in, const int* in_sizes, int n_in,
                              void* d_out, int out_size) {
    const float* x          = (const float*)d_in[0];
    const float* mask       = (const float*)d_in[1];
    const float* qkv_w      = (const float*)d_in[2];
    const float* qkv_b      = (const float*)d_in[3];
    const float* proj_w     = (const float*)d_in[4];
    const float* proj_b     = (const float*)d_in[5];
    const float* bias_table = (const float*)d_in[6];
    const int*   rel_index  = (const int*)d_in[7];
    float* out = (float*)d_out;

    bias_prep_kernel<<<64, 256>>>(bias_table, rel_index);

    cudaFuncSetAttribute(win_attn_kernel,
                         cudaFuncAttributeMaxDynamicSharedMemorySize, SMEM_BYTES);
    win_attn_kernel<<<16384, 256, SMEM_BYTES>>>(
        x, mask, qkv_w, qkv_b, proj_w, proj_b, out);
}

// round 3
// speedup vs baseline: 2.2773x; 1.0007x over previous
#include <cuda_runtime.h>
#include <cuda_bf16.h>

#define DIMC   128
#define NHEAD  4
#define NTOK   64
#define NWIN   4096
#define ST     132   // Q/K/V/x smem row stride (floats)
#define BST    388   // weight-chunk smem row stride (floats)
#define MST    65    // mask smem row stride

typedef unsigned long long ull;

__device__ __forceinline__ void ffma2(ull& d, ull a, ull b) {
    asm("fma.rn.f32x2 %0, %1, %2, %0;" : "+l"(d) : "l"(a), "l"(b));
}
__device__ __forceinline__ ull addf2(ull a, ull b) {
    ull r; asm("add.rn.f32x2 %0, %1, %2;" : "=l"(r) : "l"(a), "l"(b)); return r;
}
__device__ __forceinline__ ull pack2(float x, float y) {
    ull r; asm("mov.b64 %0, {%1, %2};" : "=l"(r) : "f"(x), "f"(y)); return r;
}
__device__ __forceinline__ float2 unpk(ull u) {
    float2 r; asm("mov.b64 {%0, %1}, %2;" : "=f"(r.x), "=f"(r.y) : "l"(u)); return r;
}

union F4U { float4 f; ull u[2]; };

// Precomputed relative-position bias, layout [h][m][row], bf16.
__device__ __nv_bfloat16 g_bias[NHEAD * NTOK * NTOK];

__global__ void bias_prep_kernel(const float* __restrict__ bias_table,
                                 const int*   __restrict__ rel_index) {
    int idx = blockIdx.x * 256 + threadIdx.x;      // 0..16383
    int h  = idx >> 12;
    int rm = idx & 4095;                           // r*64 + m
    int r  = rm >> 6, m = rm & 63;
    g_bias[h * 4096 + m * 64 + r] =
        __float2bfloat16(bias_table[rel_index[rm] * NHEAD + h]);
}

// smem float offsets
#define OFF_QS   0
#define OFF_KS   8448
#define OFF_VS   16896
#define OFF_XS   25344
#define OFF_BT   33792
#define OFF_SB   40000   // 512 floats: qkv_b(384) + proj_b(128)
#define OFF_MASK 40512   // 64*65
#define FLOATS_TOTAL 44672
#define SMEM_BYTES (FLOATS_TOTAL * 4 + NHEAD * NTOK * NTOK * 2)

__global__ __launch_bounds__(256, 1)
void win_attn_kernel(const float* __restrict__ x,
                     const float* __restrict__ mask,
                     const float* __restrict__ qkv_w,
                     const float* __restrict__ qkv_b,
                     const float* __restrict__ proj_w,
                     const float* __restrict__ proj_b,
                     float* __restrict__ out)
{
    extern __shared__ float sm[];
    float* qs     = sm + OFF_QS;
    float* ks     = sm + OFF_KS;
    float* vs     = sm + OFF_VS;
    float* xs     = sm + OFF_XS;   // x, later reused as attention output
    float* bt     = sm + OFF_BT;   // weight K-chunk [16][BST]
    float* sbias  = sm + OFF_SB;
    float* mask_s = sm + OFF_MASK;
    __nv_bfloat16* biasbf = (__nv_bfloat16*)(sm + FLOATS_TOTAL);

    const int tid  = threadIdx.x;
    const int b    = blockIdx.x;
    const int widx = b & (NWIN - 1);
    const float qscale = 0.17677669529663687f;  // 32^-0.5

    // ---- Phase 0: stage x, mask, biases, bias table ----
    {
        const float4* xg = (const float4*)(x + (size_t)b * NTOK * DIMC);
        #pragma unroll
        for (int i = 0; i < 8; i++) {
            int idx = tid + i * 256;
            int r = idx >> 5, c4 = idx & 31;
            *(float4*)&xs[r * ST + c4 * 4] = xg[idx];
        }
    }
    {
        const float4* mg = (const float4*)(mask + (size_t)widx * NTOK * NTOK);
        #pragma unroll
        for (int i = 0; i < 4; i++) {
            int idx = tid + i * 256;
            int r = idx >> 4, c4 = idx & 15;
            float4 v = mg[idx];
            mask_s[r * MST + c4 * 4 + 0] = v.x;
            mask_s[r * MST + c4 * 4 + 1] = v.y;
            mask_s[r * MST + c4 * 4 + 2] = v.z;
            mask_s[r * MST + c4 * 4 + 3] = v.w;
        }
    }
    {
        sbias[tid] = qkv_b[tid & 255] * 0.f + qkv_b[tid];  // tid<256 -> qkv_b[tid]
        int t2 = 256 + tid;
        sbias[t2] = (t2 < 384) ? qkv_b[t2] : proj_b[t2 - 384];
    }
    {
        const uint4* gb = (const uint4*)g_bias;
        uint4* sb4 = (uint4*)biasbf;
        #pragma unroll
        for (int i = 0; i < 8; i++) sb4[tid + i * 256] = gb[tid + i * 256];
    }

    // ---- Phase 1: QKV gemm (64x384x128), K-chunked, f32x2 packed ----
    const int ty = tid >> 5;   // 0..7  -> rows ty*8..+7
    const int tx = tid & 31;   // 0..31 -> cols tx*12..+11 (6 pairs)
    {
        ull acc[8][6];
        #pragma unroll
        for (int i = 0; i < 8; i++)
            #pragma unroll
            for (int j = 0; j < 6; j++) acc[i][j] = 0ULL;

        const float4* wq4 = (const float4*)qkv_w;  // [384][32] float4
        for (int kb = 0; kb < 8; kb++) {
            __syncthreads();   // previous chunk compute done before overwrite
            // stage bt[k][col] = qkv_w[col][kb*16+k], k=0..15, col=0..383
            #pragma unroll
            for (int i = 0; i < 6; i++) {
                int idx = tid + i * 256;            // 0..1535
                int col = idx >> 2, k4 = idx & 3;
                float4 g = wq4[col * 32 + kb * 4 + k4];
                int base = (k4 * 4) * BST + col;
                bt[base]           = g.x;
                bt[base + BST]     = g.y;
                bt[base + 2 * BST] = g.z;
                bt[base + 3 * BST] = g.w;
            }
            __syncthreads();

            #pragma unroll
            for (int k4 = 0; k4 < 4; k4++) {
                float4 a4[8];
                #pragma unroll
                for (int i = 0; i < 8; i++)
                    a4[i] = *(const float4*)&xs[(ty * 8 + i) * ST + kb * 16 + k4 * 4];
                #pragma unroll
                for (int kk = 0; kk < 4; kk++) {
                    ull ap[8];
                    #pragma unroll
                    for (int i = 0; i < 8; i++) {
                        float av = ((const float*)&a4[i])[kk];
                        ap[i] = pack2(av, av);
                    }
                    const float* brow = &bt[(k4 * 4 + kk) * BST + tx * 12];
                    F4U b0, b1, b2;
                    b0.f = *(const float4*)&brow[0];
                    b1.f = *(const float4*)&brow[4];
                    b2.f = *(const float4*)&brow[8];
                    const ull bp[6] = {b0.u[0], b0.u[1], b1.u[0], b1.u[1], b2.u[0], b2.u[1]};
                    #pragma unroll
                    for (int i = 0; i < 8; i++)
                        #pragma unroll
                        for (int j = 0; j < 6; j++)
                            ffma2(acc[i][j], ap[i], bp[j]);
                }
            }
        }

        // write Q (scaled) / K / V
        #pragma unroll
        for (int i = 0; i < 8; i++) {
            int r = ty * 8 + i;
            #pragma unroll
            for (int jp = 0; jp < 6; jp++) {
                float2 v = unpk(acc[i][jp]);
                int c0 = tx * 12 + jp * 2;
                #pragma unroll
                for (int e = 0; e < 2; e++) {
                    int c = c0 + e;
                    float val = (e ? v.y : v.x) + sbias[c];
                    if (c < 128)      qs[r * ST + c]       = val * qscale;
                    else if (c < 256) ks[r * ST + (c - 128)] = val;
                    else              vs[r * ST + (c - 256)] = val;
                }
            }
        }
    }
    __syncthreads();

    // ---- Phase 2: attention, thread = (head,row) ----
    {
        const int head = tid >> 6;
        const int row  = tid & 63;

        F4U q4[8];
        const float* qrow = &qs[row * ST + head * 32];
        #pragma unroll
        for (int i = 0; i < 8; i++) q4[i].f = *(const float4*)&qrow[i * 4];

        float s[64];
        float mx = -1e30f;
        #pragma unroll
        for (int m = 0; m < 64; m++) {
            const float* krow = &ks[m * ST + head * 32];
            ull a0 = 0ULL, a1 = 0ULL, a2 = 0ULL, a3 = 0ULL;
            #pragma unroll
            for (int i = 0; i < 8; i += 2) {
                F4U kv0, kv1;
                kv0.f = *(const float4*)&krow[i * 4];
                kv1.f = *(const float4*)&krow[i * 4 + 4];
                ffma2(a0, q4[i].u[0],     kv0.u[0]);
                ffma2(a1, q4[i].u[1],     kv0.u[1]);
                ffma2(a2, q4[i + 1].u[0], kv1.u[0]);
                ffma2(a3, q4[i + 1].u[1], kv1.u[1]);
            }
            float2 t = unpk(addf2(addf2(a0, a1), addf2(a2, a3)));
            float acc = t.x + t.y;
            acc += __bfloat162float(biasbf[head * 4096 + m * 64 + row]);
            acc += mask_s[row * MST + m];
            s[m] = acc;
            mx = fmaxf(mx, acc);
        }
        float sum = 0.f;
        #pragma unroll
        for (int m = 0; m < 64; m++) {
            float p = __expf(s[m] - mx);
            s[m] = p;
            sum += p;
        }
        const float rinv = 1.0f / sum;

        ull o[16];
        #pragma unroll
        for (int j = 0; j < 16; j++) o[j] = 0ULL;
        #pragma unroll
        for (int m = 0; m < 64; m++) {
            ull pp = pack2(s[m], s[m]);
            const float* vrow = &vs[m * ST + head * 32];
            #pragma unroll
            for (int i = 0; i < 8; i++) {
                F4U vv; vv.f = *(const float4*)&vrow[i * 4];
                ffma2(o[i * 2],     pp, vv.u[0]);
                ffma2(o[i * 2 + 1], pp, vv.u[1]);
            }
        }
        float* aor = &xs[row * ST + head * 32];
        #pragma unroll
        for (int j = 0; j < 16; j++) {
            float2 v = unpk(o[j]);
            aor[j * 2]     = v.x * rinv;
            aor[j * 2 + 1] = v.y * rinv;
        }
    }

    // ---- Phase 3: proj gemm (64x128x128), K-chunked, f32x2 ----
    {
        ull pacc[8][2];
        #pragma unroll
        for (int i = 0; i < 8; i++) { pacc[i][0] = 0ULL; pacc[i][1] = 0ULL; }

        const float4* wp4 = (const float4*)proj_w;   // [128][32] float4
        for (int kb = 0; kb < 8; kb++) {
            __syncthreads();
            #pragma unroll
            for (int i = 0; i < 2; i++) {
                int idx = tid + i * 256;             // 0..511
                int col = idx >> 2, k4 = idx & 3;
                float4 g = wp4[col * 32 + kb * 4 + k4];
                int base = (k4 * 4) * BST + col;
                bt[base]           = g.x;
                bt[base + BST]     = g.y;
                bt[base + 2 * BST] = g.z;
                bt[base + 3 * BST] = g.w;
            }
            __syncthreads();

            #pragma unroll
            for (int k4 = 0; k4 < 4; k4++) {
                float4 a4[8];
                #pragma unroll
                for (int i = 0; i < 8; i++)
                    a4[i] = *(const float4*)&xs[(ty * 8 + i) * ST + kb * 16 + k4 * 4];
                #pragma unroll
                for (int kk = 0; kk < 4; kk++) {
                    const float* brow = &bt[(k4 * 4 + kk) * BST + tx * 4];
                    F4U bv; bv.f = *(const float4*)&brow[0];
                    #pragma unroll
                    for (int i = 0; i < 8; i++) {
                        float av = ((const float*)&a4[i])[kk];
                        ull ap = pack2(av, av);
                        ffma2(pacc[i][0], ap, bv.u[0]);
                        ffma2(pacc[i][1], ap, bv.u[1]);
                    }
                }
            }
        }

        float* og = out + (size_t)b * NTOK * DIMC;
        int c0 = tx * 4;
        float pb0 = sbias[384 + c0];
        float pb1 = sbias[384 + c0 + 1];
        float pb2 = sbias[384 + c0 + 2];
        float pb3 = sbias[384 + c0 + 3];
        #pragma unroll
        for (int i = 0; i < 8; i++) {
            float2 v0 = unpk(pacc[i][0]);
            float2 v1 = unpk(pacc[i][1]);
            float4 o;
            o.x = v0.x + pb0; o.y = v0.y + pb1;
            o.z = v1.x + pb2; o.w = v1.y + pb3;
            *(float4*)&og[(ty * 8 + i) * DIMC + c0] = o;
        }
    }
}

extern "C" void kernel_launch(void* const* d_in, const int* in_sizes, int n_in,
                              void* d_out, int out_size) {
    const float* x          = (const float*)d_in[0];
    const float* mask       = (const float*)d_in[1];
    const float* qkv_w      = (const float*)d_in[2];
    const float* qkv_b      = (const float*)d_in[3];
    const float* proj_w     = (const float*)d_in[4];
    const float* proj_b     = (const float*)d_in[5];
    const float* bias_table = (const float*)d_in[6];
    const int*   rel_index  = (const int*)d_in[7];
    float* out = (float*)d_out;

    bias_prep_kernel<<<64, 256>>>(bias_table, rel_index);

    cudaFuncSetAttribute(win_attn_kernel,
                         cudaFuncAttributeMaxDynamicSharedMemorySize, SMEM_BYTES);
    win_attn_kernel<<<16384, 256, SMEM_BYTES>>>(
        x, mask, qkv_w, qkv_b, proj_w, proj_b, out);
}

// round 5
// speedup vs baseline: 3.6883x; 1.6196x over previous
#include <cuda_runtime.h>
#include <cuda_bf16.h>
#include <cstdint>

typedef unsigned long long ull;
typedef uint32_t u32;

__device__ __forceinline__ void ffma2(ull& d, ull a, ull b) {
    asm("fma.rn.f32x2 %0, %1, %2, %0;" : "+l"(d) : "l"(a), "l"(b));
}
__device__ __forceinline__ ull addf2(ull a, ull b) {
    ull r; asm("add.rn.f32x2 %0, %1, %2;" : "=l"(r) : "l"(a), "l"(b)); return r;
}
__device__ __forceinline__ ull pack2(float x, float y) {
    ull r; asm("mov.b64 %0, {%1, %2};" : "=l"(r) : "f"(x), "f"(y)); return r;
}
__device__ __forceinline__ float2 unpk(ull u) {
    float2 r; asm("mov.b64 {%0, %1}, %2;" : "=f"(r.x), "=f"(r.y) : "l"(u)); return r;
}
union F4U { float4 f; ull u[2]; };

// bf16 m16n8k16 MMA, fp32 accumulate in-place
__device__ __forceinline__ void mma16816(float* c, const u32* a, const u32* b) {
    asm volatile(
        "mma.sync.aligned.m16n8k16.row.col.f32.bf16.bf16.f32 "
        "{%0,%1,%2,%3}, {%4,%5,%6,%7}, {%8,%9}, {%0,%1,%2,%3};"
        : "+f"(c[0]), "+f"(c[1]), "+f"(c[2]), "+f"(c[3])
        : "r"(a[0]), "r"(a[1]), "r"(a[2]), "r"(a[3]), "r"(b[0]), "r"(b[1]));
}

__device__ __forceinline__ void split8(float4 v, ull& hi, ull& lo) {
    __nv_bfloat16 h0 = __float2bfloat16(v.x), h1 = __float2bfloat16(v.y),
                  h2 = __float2bfloat16(v.z), h3 = __float2bfloat16(v.w);
    __nv_bfloat16 l0 = __float2bfloat16(v.x - __bfloat162float(h0));
    __nv_bfloat16 l1 = __float2bfloat16(v.y - __bfloat162float(h1));
    __nv_bfloat16 l2 = __float2bfloat16(v.z - __bfloat162float(h2));
    __nv_bfloat16 l3 = __float2bfloat16(v.w - __bfloat162float(h3));
    u32 ha = (u32)__bfloat16_as_ushort(h0) | ((u32)__bfloat16_as_ushort(h1) << 16);
    u32 hb = (u32)__bfloat16_as_ushort(h2) | ((u32)__bfloat16_as_ushort(h3) << 16);
    u32 la = (u32)__bfloat16_as_ushort(l0) | ((u32)__bfloat16_as_ushort(l1) << 16);
    u32 lb = (u32)__bfloat16_as_ushort(l2) | ((u32)__bfloat16_as_ushort(l3) << 16);
    hi = (ull)ha | ((ull)hb << 32);
    lo = (ull)la | ((ull)lb << 32);
}

// prepped globals: weights split to bf16 hi/lo, row-major u32 pairs [512 rows][64 u32]
__device__ __align__(16) u32 g_whi[512 * 64];
__device__ __align__(16) u32 g_wlo[512 * 64];
__device__ __nv_bfloat16 g_bias[4 * 64 * 64];   // [h][m][row]

__global__ void wprep_kernel(const float* __restrict__ qkv_w,
                             const float* __restrict__ proj_w) {
    int g = blockIdx.x * 256 + threadIdx.x;     // 0..16383
    int row = g >> 5, c4 = g & 31;
    const float* src = (row < 384) ? &qkv_w[row * 128 + c4 * 4]
                                   : &proj_w[(row - 384) * 128 + c4 * 4];
    ull hi, lo; split8(*(const float4*)src, hi, lo);
    *(ull*)&g_whi[row * 64 + c4 * 2] = hi;
    *(ull*)&g_wlo[row * 64 + c4 * 2] = lo;
}
__global__ void bias_prep_kernel(const float* __restrict__ bias_table,
                                 const int* __restrict__ rel_index) {
    int idx = blockIdx.x * 256 + threadIdx.x;
    int h = idx >> 12, rm = idx & 4095;
    int r = rm >> 6, m = rm & 63;
    g_bias[h * 4096 + m * 64 + r] = __float2bfloat16(bias_table[rel_index[rm] * 4 + h]);
}

// smem layout (float indices)
#define QST 132
#define XST 68          // u32 stride, 136 bf16 per row
#define OFF_QS   0
#define OFF_KS   8448
#define OFF_VS   16896
#define OFF_XH   25344  // u32[64*68]
#define OFF_XL   29696
#define OFF_WH   34048  // u32[128*68]
#define OFF_WL   42752
#define OFF_MASK 51456  // 64*65
#define OFF_SB   55616  // 512
#define FTOT     56128
#define SMEM_BYTES (FTOT * 4)
#define MST 65

__global__ __launch_bounds__(256, 1)
void win_attn_mma(const float* __restrict__ x,
                  const float* __restrict__ mask,
                  const float* __restrict__ qkv_b,
                  const float* __restrict__ proj_b,
                  float* __restrict__ out)
{
    extern __shared__ float smf[];
    float* qs = smf + OFF_QS;
    float* ks = smf + OFF_KS;
    float* vs = smf + OFF_VS;
    u32* xh = (u32*)(smf + OFF_XH);
    u32* xl = (u32*)(smf + OFF_XL);
    u32* wh = (u32*)(smf + OFF_WH);
    u32* wl = (u32*)(smf + OFF_WL);
    float* mask_s = smf + OFF_MASK;
    float* sb     = smf + OFF_SB;

    const int tid = threadIdx.x;
    const int w = tid >> 5, lane = tid & 31;
    const int wm = w & 3, wn = w >> 2;       // 4 x 2 warp grid
    const int g = lane >> 2, t = lane & 3;
    const int b = blockIdx.x;
    const float qscale = 0.17677669529663687f;

    // ---- phase 0 ----
    {
        const float4* xg = (const float4*)(x + (size_t)b * 8192);
        #pragma unroll
        for (int i = 0; i < 8; i++) {
            int idx = tid + i * 256;           // 0..2047
            int row = idx >> 5, c4 = idx & 31;
            ull hi, lo; split8(xg[idx], hi, lo);
            *(ull*)&xh[row * XST + c4 * 2] = hi;
            *(ull*)&xl[row * XST + c4 * 2] = lo;
        }
        const float4* mg = (const float4*)(mask + (size_t)(b & 4095) * 4096);
        #pragma unroll
        for (int i = 0; i < 4; i++) {
            int idx = tid + i * 256;
            int r = idx >> 4, c4 = idx & 15;
            float4 v = mg[idx];
            mask_s[r * MST + c4 * 4]     = v.x;
            mask_s[r * MST + c4 * 4 + 1] = v.y;
            mask_s[r * MST + c4 * 4 + 2] = v.z;
            mask_s[r * MST + c4 * 4 + 3] = v.w;
        }
        sb[tid] = qkv_b[tid];
        int t2 = 256 + tid;
        sb[t2] = (t2 < 384) ? qkv_b[t2] : proj_b[t2 - 384];
    }
    __syncthreads();

    // ---- QKV + proj via mma: 4 chunks of 128 output cols (3 qkv + 1 proj later) ----
    const int rowA0 = wm * 16 + g;
    for (int c = 0; c < 3; c++) {
        // stage weight chunk rows c*128..+127
        {
            const uint4* sh = (const uint4*)(g_whi + c * 128 * 64);
            const uint4* sl = (const uint4*)(g_wlo + c * 128 * 64);
            #pragma unroll
            for (int i = 0; i < 8; i++) {
                int idx = tid + i * 256;       // 0..2047
                int r = idx >> 4, q = idx & 15;
                *(uint4*)&wh[r * XST + q * 4] = sh[idx];
                *(uint4*)&wl[r * XST + q * 4] = sl[idx];
            }
        }
        __syncthreads();

        float acc[8][4];
        #pragma unroll
        for (int n = 0; n < 8; n++)
            #pragma unroll
            for (int j = 0; j < 4; j++) acc[n][j] = 0.f;

        const u32* xhr0 = xh + rowA0 * XST;
        const u32* xhr1 = xh + (rowA0 + 8) * XST;
        const u32* xlr0 = xl + rowA0 * XST;
        const u32* xlr1 = xl + (rowA0 + 8) * XST;
        #pragma unroll
        for (int ksI = 0; ksI < 8; ksI++) {
            int kb = ksI * 8 + t;
            u32 ah[4] = { xhr0[kb], xhr1[kb], xhr0[kb + 4], xhr1[kb + 4] };
            u32 al[4] = { xlr0[kb], xlr1[kb], xlr0[kb + 4], xlr1[kb + 4] };
            #pragma unroll
            for (int n = 0; n < 8; n++) {
                int wrow = wn * 64 + n * 8 + g;
                const u32* whr = wh + wrow * XST;
                const u32* wlr = wl + wrow * XST;
                u32 bh[2] = { whr[kb], whr[kb + 4] };
                u32 bl[2] = { wlr[kb], wlr[kb + 4] };
                mma16816(acc[n], ah, bh);
                mma16816(acc[n], ah, bl);
                mma16816(acc[n], al, bh);
            }
        }

        // writeback with bias (+scale for Q chunk)
        float* dst = (c == 0) ? qs : (c == 1) ? ks : vs;
        #pragma unroll
        for (int n = 0; n < 8; n++) {
            int col = wn * 64 + n * 8 + t * 2;       // within-chunk col (pair)
            float b0 = sb[c * 128 + col], b1 = sb[c * 128 + col + 1];
            float2 v0 = make_float2(acc[n][0] + b0, acc[n][1] + b1);
            float2 v1 = make_float2(acc[n][2] + b0, acc[n][3] + b1);
            if (c == 0) { v0.x *= qscale; v0.y *= qscale; v1.x *= qscale; v1.y *= qscale; }
            *(float2*)&dst[rowA0 * QST + col]       = v0;
            *(float2*)&dst[(rowA0 + 8) * QST + col] = v1;
        }
        __syncthreads();
    }

    // ---- attention: thread = (head, row), scalar f32x2 ----
    {
        const int head = tid >> 6;
        const int row  = tid & 63;
        F4U q4[8];
        const float* qrow = &qs[row * QST + head * 32];
        #pragma unroll
        for (int i = 0; i < 8; i++) q4[i].f = *(const float4*)&qrow[i * 4];

        float s[64], mx = -1e30f;
        #pragma unroll 4
        for (int m = 0; m < 64; m++) {
            const float* kr = &ks[m * QST + head * 32];
            ull a0 = 0ULL, a1 = 0ULL, a2 = 0ULL, a3 = 0ULL;
            #pragma unroll
            for (int i = 0; i < 8; i += 2) {
                F4U k0, k1;
                k0.f = *(const float4*)&kr[i * 4];
                k1.f = *(const float4*)&kr[i * 4 + 4];
                ffma2(a0, q4[i].u[0],     k0.u[0]);
                ffma2(a1, q4[i].u[1],     k0.u[1]);
                ffma2(a2, q4[i + 1].u[0], k1.u[0]);
                ffma2(a3, q4[i + 1].u[1], k1.u[1]);
            }
            float2 tt = unpk(addf2(addf2(a0, a1), addf2(a2, a3)));
            float sc = tt.x + tt.y
                     + __bfloat162float(g_bias[head * 4096 + m * 64 + row])
                     + mask_s[row * MST + m];
            s[m] = sc; mx = fmaxf(mx, sc);
        }
        float sum = 0.f;
        #pragma unroll
        for (int m = 0; m < 64; m++) { float p = __expf(s[m] - mx); s[m] = p; sum += p; }
        const float rinv = 1.0f / sum;

        ull o[16];
        #pragma unroll
        for (int j = 0; j < 16; j++) o[j] = 0ULL;
        #pragma unroll 4
        for (int m = 0; m < 64; m++) {
            ull pp = pack2(s[m], s[m]);
            const float* vr = &vs[m * QST + head * 32];
            #pragma unroll
            for (int i = 0; i < 8; i++) {
                F4U vv; vv.f = *(const float4*)&vr[i * 4];
                ffma2(o[i * 2],     pp, vv.u[0]);
                ffma2(o[i * 2 + 1], pp, vv.u[1]);
            }
        }
        __syncthreads();   // everyone done reading xh-era data; safe to overwrite xh/xl
        // ao -> xh/xl (bf16 split) for proj MMA
        #pragma unroll
        for (int p = 0; p < 16; p++) {
            float2 v = unpk(o[p]);
            v.x *= rinv; v.y *= rinv;
            __nv_bfloat16 h0 = __float2bfloat16(v.x), h1 = __float2bfloat16(v.y);
            __nv_bfloat16 l0 = __float2bfloat16(v.x - __bfloat162float(h0));
            __nv_bfloat16 l1 = __float2bfloat16(v.y - __bfloat162float(h1));
            xh[row * XST + head * 16 + p] =
                (u32)__bfloat16_as_ushort(h0) | ((u32)__bfloat16_as_ushort(h1) << 16);
            xl[row * XST + head * 16 + p] =
                (u32)__bfloat16_as_ushort(l0) | ((u32)__bfloat16_as_ushort(l1) << 16);
        }
    }
    // stage proj weights (rows 384..511)
    {
        const uint4* sh = (const uint4*)(g_whi + 384 * 64);
        const uint4* sl = (const uint4*)(g_wlo + 384 * 64);
        #pragma unroll
        for (int i = 0; i < 8; i++) {
            int idx = tid + i * 256;
            int r = idx >> 4, q = idx & 15;
            *(uint4*)&wh[r * XST + q * 4] = sh[idx];
            *(uint4*)&wl[r * XST + q * 4] = sl[idx];
        }
    }
    __syncthreads();

    // ---- proj mma, write out ----
    {
        float acc[8][4];
        #pragma unroll
        for (int n = 0; n < 8; n++)
            #pragma unroll
            for (int j = 0; j < 4; j++) acc[n][j] = 0.f;
        const u32* xhr0 = xh + rowA0 * XST;
        const u32* xhr1 = xh + (rowA0 + 8) * XST;
        const u32* xlr0 = xl + rowA0 * XST;
        const u32* xlr1 = xl + (rowA0 + 8) * XST;
        #pragma unroll
        for (int ksI = 0; ksI < 8; ksI++) {
            int kb = ksI * 8 + t;
            u32 ah[4] = { xhr0[kb], xhr1[kb], xhr0[kb + 4], xhr1[kb + 4] };
            u32 al[4] = { xlr0[kb], xlr1[kb], xlr0[kb + 4], xlr1[kb + 4] };
            #pragma unroll
            for (int n = 0; n < 8; n++) {
                int wrow = wn * 64 + n * 8 + g;
                const u32* whr = wh + wrow * XST;
                const u32* wlr = wl + wrow * XST;
                u32 bh[2] = { whr[kb], whr[kb + 4] };
                u32 bl[2] = { wlr[kb], wlr[kb + 4] };
                mma16816(acc[n], ah, bh);
                mma16816(acc[n], ah, bl);
                mma16816(acc[n], al, bh);
            }
        }
        float* og = out + (size_t)b * 8192;
        #pragma unroll
        for (int n = 0; n < 8; n++) {
            int col = wn * 64 + n * 8 + t * 2;
            float b0 = sb[384 + col], b1 = sb[384 + col + 1];
            *(float2*)&og[rowA0 * 128 + col] =
                make_float2(acc[n][0] + b0, acc[n][1] + b1);
            *(float2*)&og[(rowA0 + 8) * 128 + col] =
                make_float2(acc[n][2] + b0, acc[n][3] + b1);
        }
    }
}

extern "C" void kernel_launch(void* const* d_in, const int* in_sizes, int n_in,
                              void* d_out, int out_size) {
    const float* x          = (const float*)d_in[0];
    const float* mask       = (const float*)d_in[1];
    const float* qkv_w      = (const float*)d_in[2];
    const float* qkv_b      = (const float*)d_in[3];
    const float* proj_w     = (const float*)d_in[4];
    const float* proj_b     = (const float*)d_in[5];
    const float* bias_table = (const float*)d_in[6];
    const int*   rel_index  = (const int*)d_in[7];
    float* out = (float*)d_out;

    wprep_kernel<<<64, 256>>>(qkv_w, proj_w);
    bias_prep_kernel<<<64, 256>>>(bias_table, rel_index);

    cudaFuncSetAttribute(win_attn_mma,
                         cudaFuncAttributeMaxDynamicSharedMemorySize, SMEM_BYTES);
    win_attn_mma<<<16384, 256, SMEM_BYTES>>>(x, mask, qkv_b, proj_b, out);
}

// round 6
// speedup vs baseline: 5.1475x; 1.3956x over previous
#include <cuda_runtime.h>
#include <cuda_bf16.h>
#include <cstdint>

typedef uint32_t u32;

// ---------- helpers ----------
__device__ __forceinline__ u32 smem_u32(const void* p) {
    u32 a; asm("{ .reg .u64 t; cvta.to.shared.u64 t, %1; cvt.u32.u64 %0, t; }" : "=r"(a) : "l"(p));
    return a;
}
__device__ __forceinline__ void mma16816(float* c, const u32* a, const u32* b) {
    asm volatile(
        "mma.sync.aligned.m16n8k16.row.col.f32.bf16.bf16.f32 "
        "{%0,%1,%2,%3}, {%4,%5,%6,%7}, {%8,%9}, {%0,%1,%2,%3};"
        : "+f"(c[0]), "+f"(c[1]), "+f"(c[2]), "+f"(c[3])
        : "r"(a[0]), "r"(a[1]), "r"(a[2]), "r"(a[3]), "r"(b[0]), "r"(b[1]));
}
#define LDSM4(R, A) asm volatile( \
    "ldmatrix.sync.aligned.m8n8.x4.shared.b16 {%0,%1,%2,%3}, [%4];" \
    : "=r"((R)[0]), "=r"((R)[1]), "=r"((R)[2]), "=r"((R)[3]) : "r"(A))
#define LDSM4T(R, A) asm volatile( \
    "ldmatrix.sync.aligned.m8n8.x4.trans.shared.b16 {%0,%1,%2,%3}, [%4];" \
    : "=r"((R)[0]), "=r"((R)[1]), "=r"((R)[2]), "=r"((R)[3]) : "r"(A))
#define CPA(d, s) asm volatile( \
    "{ .reg .u64 p; cvta.to.global.u64 p, %1; cp.async.cg.shared.global [%0], [p], 16; }" \
    :: "r"(d), "l"(s) : "memory")
#define CPCOMMIT() asm volatile("cp.async.commit_group;" ::: "memory")
#define CPWAIT0()  asm volatile("cp.async.wait_group 0;" ::: "memory")

__device__ __forceinline__ void split2(float a, float b, u32& h, u32& l) {
    __nv_bfloat16 ha = __float2bfloat16(a), hb = __float2bfloat16(b);
    h = (u32)__bfloat16_as_ushort(ha) | ((u32)__bfloat16_as_ushort(hb) << 16);
    __nv_bfloat16 la = __float2bfloat16(a - __bfloat162float(ha));
    __nv_bfloat16 lb = __float2bfloat16(b - __bfloat162float(hb));
    l = (u32)__bfloat16_as_ushort(la) | ((u32)__bfloat16_as_ushort(lb) << 16);
}
__device__ __forceinline__ float bflo(u32 u) {
    return __bfloat162float(__ushort_as_bfloat16((unsigned short)(u & 0xffff)));
}
__device__ __forceinline__ float bfhi(u32 u) {
    return __bfloat162float(__ushort_as_bfloat16((unsigned short)(u >> 16)));
}

// ---------- prepped globals ----------
// weights split bf16 hi/lo, row-major [512 out-rows][64 u32 (128 bf16 k)]
__device__ __align__(16) u32 g_whi[512 * 64];
__device__ __align__(16) u32 g_wlo[512 * 64];
// bias packed u32 (two key-cols per u32): [h][row][32]
__device__ u32 g_bias2[4 * 64 * 32];

__global__ void wprep_kernel(const float* __restrict__ qkv_w,
                             const float* __restrict__ proj_w) {
    int gidx = blockIdx.x * 256 + threadIdx.x;    // 0..16383
    int row = gidx >> 5, c4 = gidx & 31;
    const float* src = (row < 384) ? &qkv_w[row * 128 + c4 * 4]
                                   : &proj_w[(row - 384) * 128 + c4 * 4];
    float4 v = *(const float4*)src;
    u32 h0, l0, h1, l1;
    split2(v.x, v.y, h0, l0);
    split2(v.z, v.w, h1, l1);
    g_whi[row * 64 + c4 * 2]     = h0;
    g_whi[row * 64 + c4 * 2 + 1] = h1;
    g_wlo[row * 64 + c4 * 2]     = l0;
    g_wlo[row * 64 + c4 * 2 + 1] = l1;
}
__global__ void bias_prep_kernel(const float* __restrict__ bias_table,
                                 const int* __restrict__ rel_index) {
    int idx = blockIdx.x * 256 + threadIdx.x;   // 0..8191: h*2048 + row*32 + j
    int h = idx >> 11, rm = idx & 2047;
    int row = rm >> 5, j = rm & 31;
    float b0 = bias_table[rel_index[row * 64 + 2 * j] * 4 + h];
    float b1 = bias_table[rel_index[row * 64 + 2 * j + 1] * 4 + h];
    u32 p = (u32)__bfloat16_as_ushort(__float2bfloat16(b0))
          | ((u32)__bfloat16_as_ushort(__float2bfloat16(b1)) << 16);
    g_bias2[idx] = p;
}

// ---------- smem layout (u32 units) ----------
#define OFF_QH 0u
#define OFF_QL 4352u
#define OFF_KH 8704u
#define OFF_KL 13056u
#define OFF_VH 17408u
#define OFF_VL 21760u
#define OFF_W  26112u      // 2 buffers x (WH 4352 + WL 4352)
#define OFF_MK 43520u      // mask [64][68] floats
#define OFF_BI 47872u      // bias u32 [4][64][33]
#define OFF_SB 56320u      // 512 floats
#define SMEM_U32 56832u
#define SMEM_BYTES (SMEM_U32 * 4u)

__device__ __forceinline__ void cp_chunk(u32 sb32, int c, int buf, int tid) {
    const uint4* sH = (const uint4*)g_whi + c * 1024;   // 64 rows x 16 uint4
    const uint4* sL = (const uint4*)g_wlo + c * 1024;
    u32 dH = sb32 + (OFF_W + (u32)buf * 8704u) * 4u;
    u32 dL = dH + 4352u * 4u;
    #pragma unroll
    for (int i = 0; i < 4; i++) {
        int idx = tid + i * 256;
        int row = idx >> 4, q4 = idx & 15;
        u32 off = (u32)(row * 68 + q4 * 4) * 4u;
        CPA(dH + off, sH + idx);
        CPA(dL + off, sL + idx);
    }
    CPCOMMIT();
}

__global__ __launch_bounds__(256, 1)
void win_attn6(const float* __restrict__ x,
               const float* __restrict__ mask,
               const float* __restrict__ qkv_b,
               const float* __restrict__ proj_b,
               float* __restrict__ out)
{
    extern __shared__ u32 su[];
    float* sbf = (float*)(su + OFF_SB);
    float* mkf = (float*)(su + OFF_MK);
    const int tid = threadIdx.x;
    const int w = tid >> 5, lane = tid & 31;
    const int g = lane >> 2, t = lane & 3;
    const int mt = w & 3, nh = w >> 2;           // gemm roles
    const int h = w >> 1, half = w & 1;          // attention roles
    const int r0 = half * 32;
    const int b = blockIdx.x;
    const u32 sb32 = smem_u32(su);
    const float qscale = 0.17677669529663687f;

    // ldmatrix lane address patterns
    const int aRow = lane & 15;
    const u32 aK = (u32)(lane >> 4) * 4u;                  // A / V-trans pattern
    const int bN = (lane & 7) + ((lane >> 4) << 3);        // B pattern
    const u32 bK = (lane & 8) ? 4u : 0u;

    // ---- prologue: start weight chunk 0, stage mask/bias/sb, load X A-frags ----
    cp_chunk(sb32, 0, 0, tid);
    {
        const float4* mg = (const float4*)(mask + (size_t)(b & 4095) * 4096);
        #pragma unroll
        for (int i = 0; i < 4; i++) {
            int idx = tid + i * 256;
            int r = idx >> 4, c4 = idx & 15;
            *(float4*)&mkf[r * 68 + c4 * 4] = mg[idx];
        }
        #pragma unroll
        for (int i = 0; i < 32; i++) {
            int idx = tid + i * 256;          // h*2048 + row*32 + j
            int hh = idx >> 11, rm = idx & 2047;
            int row = rm >> 5, j = rm & 31;
            su[OFF_BI + (u32)((hh * 64 + row) * 33 + j)] = g_bias2[idx];
        }
        sbf[tid] = qkv_b[tid];
        int t2 = 256 + tid;
        sbf[t2] = (t2 < 384) ? qkv_b[t2] : proj_b[t2 - 384];
    }

    // X A-fragments from global (per-thread, bf16-split in registers)
    u32 axh[8][4], axl[8][4];
    {
        const float* xb = x + (size_t)b * 8192 + (size_t)(mt * 16 + g) * 128 + 2 * t;
        #pragma unroll
        for (int ks = 0; ks < 8; ks++) {
            #pragma unroll
            for (int j = 0; j < 4; j++) {
                int roff = (j & 1) * 8 * 128;
                int koff = ks * 16 + (j >> 1) * 8;
                float2 v = *(const float2*)(xb + roff + koff);
                split2(v.x, v.y, axh[ks][j], axl[ks][j]);
            }
        }
    }

    // ---- QKV gemm: 6 chunks of 64 cols, cp.async double-buffered ----
    for (int c = 0; c < 6; c++) {
        CPWAIT0();
        __syncthreads();
        cp_chunk(sb32, c + 1, (c + 1) & 1, tid);

        float acc[4][4];
        #pragma unroll
        for (int n = 0; n < 4; n++)
            #pragma unroll
            for (int j = 0; j < 4; j++) acc[n][j] = 0.f;

        const u32 wb = OFF_W + (u32)(c & 1) * 8704u;
        #pragma unroll
        for (int ks = 0; ks < 8; ks++) {
            #pragma unroll
            for (int np = 0; np < 2; np++) {
                u32 bh[4], bl[4];
                u32 bd = sb32 + (wb + (u32)((nh * 32 + np * 16 + bN) * 68) + (u32)(ks * 8) + bK) * 4u;
                LDSM4(bh, bd);
                LDSM4(bl, bd + 4352u * 4u);
                #pragma unroll
                for (int ntl = 0; ntl < 2; ntl++) {
                    int nt = np * 2 + ntl;
                    mma16816(acc[nt], axh[ks], bh + ntl * 2);
                    mma16816(acc[nt], axh[ks], bl + ntl * 2);
                    mma16816(acc[nt], axl[ks], bh + ntl * 2);
                }
            }
        }
        // epilogue: +bias, split to bf16 hi/lo, store to Q/K/V
        u32 dOff = (c < 2) ? OFF_QH : (c < 4) ? OFF_KH : OFF_VH;
        int colb = (c & 1) * 64 + nh * 32;
        #pragma unroll
        for (int nt = 0; nt < 4; nt++) {
            int col = colb + nt * 8 + 2 * t;
            float b0 = sbf[c * 64 + nh * 32 + nt * 8 + 2 * t];
            float b1 = sbf[c * 64 + nh * 32 + nt * 8 + 2 * t + 1];
            u32 h0, l0, h1, l1;
            split2(acc[nt][0] + b0, acc[nt][1] + b1, h0, l0);
            split2(acc[nt][2] + b0, acc[nt][3] + b1, h1, l1);
            int rw = mt * 16 + g;
            su[dOff + (u32)(rw * 68 + (col >> 1))]              = h0;
            su[dOff + 4352u + (u32)(rw * 68 + (col >> 1))]      = l0;
            su[dOff + (u32)((rw + 8) * 68 + (col >> 1))]        = h1;
            su[dOff + 4352u + (u32)((rw + 8) * 68 + (col >> 1))]= l1;
        }
    }
    __syncthreads();

    // ---- attention: warp = (head h, row-half), rows r0..r0+31 ----
    // Q A-fragments
    u32 aqh[2][2][4], aql[2][2][4];
    #pragma unroll
    for (int mt2 = 0; mt2 < 2; mt2++)
        #pragma unroll
        for (int ks = 0; ks < 2; ks++) {
            u32 ad = sb32 + (OFF_QH + (u32)((r0 + mt2 * 16 + aRow) * 68 + h * 16 + ks * 8) + aK) * 4u;
            LDSM4(aqh[mt2][ks], ad);
            LDSM4(aql[mt2][ks], ad + 4352u * 4u);
        }
    // S = Q K^T (split x3)
    float sacc[2][8][4];
    #pragma unroll
    for (int i = 0; i < 2; i++)
        #pragma unroll
        for (int n = 0; n < 8; n++)
            #pragma unroll
            for (int j = 0; j < 4; j++) sacc[i][n][j] = 0.f;
    #pragma unroll
    for (int ks = 0; ks < 2; ks++) {
        #pragma unroll
        for (int np = 0; np < 4; np++) {
            u32 bh[4], bl[4];
            u32 bd = sb32 + (OFF_KH + (u32)((np * 16 + bN) * 68 + h * 16 + ks * 8) + bK) * 4u;
            LDSM4(bh, bd);
            LDSM4(bl, bd + 4352u * 4u);
            #pragma unroll
            for (int mt2 = 0; mt2 < 2; mt2++)
                #pragma unroll
                for (int ntl = 0; ntl < 2; ntl++) {
                    int nt = np * 2 + ntl;
                    mma16816(sacc[mt2][nt], aqh[mt2][ks], bh + ntl * 2);
                    mma16816(sacc[mt2][nt], aqh[mt2][ks], bl + ntl * 2);
                    mma16816(sacc[mt2][nt], aql[mt2][ks], bh + ntl * 2);
                }
        }
    }
    // softmax on fragments
    float mx[2][2] = {{-1e30f, -1e30f}, {-1e30f, -1e30f}};
    #pragma unroll
    for (int mt2 = 0; mt2 < 2; mt2++) {
        #pragma unroll
        for (int nt = 0; nt < 8; nt++) {
            int row0 = r0 + mt2 * 16 + g;
            float2 mk0 = *(float2*)(mkf + row0 * 68 + nt * 8 + 2 * t);
            float2 mk1 = *(float2*)(mkf + (row0 + 8) * 68 + nt * 8 + 2 * t);
            u32 bb0 = su[OFF_BI + (u32)((h * 64 + row0) * 33 + nt * 4 + t)];
            u32 bb1 = su[OFF_BI + (u32)((h * 64 + row0 + 8) * 33 + nt * 4 + t)];
            float s0 = sacc[mt2][nt][0] * qscale + bflo(bb0) + mk0.x;
            float s1 = sacc[mt2][nt][1] * qscale + bfhi(bb0) + mk0.y;
            float s2 = sacc[mt2][nt][2] * qscale + bflo(bb1) + mk1.x;
            float s3 = sacc[mt2][nt][3] * qscale + bfhi(bb1) + mk1.y;
            sacc[mt2][nt][0] = s0; sacc[mt2][nt][1] = s1;
            sacc[mt2][nt][2] = s2; sacc[mt2][nt][3] = s3;
            mx[mt2][0] = fmaxf(mx[mt2][0], fmaxf(s0, s1));
            mx[mt2][1] = fmaxf(mx[mt2][1], fmaxf(s2, s3));
        }
    }
    #pragma unroll
    for (int mt2 = 0; mt2 < 2; mt2++)
        #pragma unroll
        for (int d = 0; d < 2; d++) {
            float v = mx[mt2][d];
            v = fmaxf(v, __shfl_xor_sync(0xffffffff, v, 1));
            v = fmaxf(v, __shfl_xor_sync(0xffffffff, v, 2));
            mx[mt2][d] = v;
        }
    float sum[2][2] = {{0.f, 0.f}, {0.f, 0.f}};
    #pragma unroll
    for (int mt2 = 0; mt2 < 2; mt2++)
        #pragma unroll
        for (int nt = 0; nt < 8; nt++) {
            float p0 = __expf(sacc[mt2][nt][0] - mx[mt2][0]);
            float p1 = __expf(sacc[mt2][nt][1] - mx[mt2][0]);
            float p2 = __expf(sacc[mt2][nt][2] - mx[mt2][1]);
            float p3 = __expf(sacc[mt2][nt][3] - mx[mt2][1]);
            sacc[mt2][nt][0] = p0; sacc[mt2][nt][1] = p1;
            sacc[mt2][nt][2] = p2; sacc[mt2][nt][3] = p3;
            sum[mt2][0] += p0 + p1;
            sum[mt2][1] += p2 + p3;
        }
    float rinv[2][2];
    #pragma unroll
    for (int mt2 = 0; mt2 < 2; mt2++)
        #pragma unroll
        for (int d = 0; d < 2; d++) {
            float v = sum[mt2][d];
            v += __shfl_xor_sync(0xffffffff, v, 1);
            v += __shfl_xor_sync(0xffffffff, v, 2);
            rinv[mt2][d] = 1.0f / v;
        }
    // O = P V (P packed in-register to A-frags, split x3)
    float oacc[2][4][4];
    #pragma unroll
    for (int i = 0; i < 2; i++)
        #pragma unroll
        for (int n = 0; n < 4; n++)
            #pragma unroll
            for (int j = 0; j < 4; j++) oacc[i][n][j] = 0.f;
    #pragma unroll
    for (int kt = 0; kt < 4; kt++) {
        u32 ph[2][4], pl[2][4];
        #pragma unroll
        for (int mt2 = 0; mt2 < 2; mt2++) {
            split2(sacc[mt2][2 * kt][0],     sacc[mt2][2 * kt][1],     ph[mt2][0], pl[mt2][0]);
            split2(sacc[mt2][2 * kt][2],     sacc[mt2][2 * kt][3],     ph[mt2][1], pl[mt2][1]);
            split2(sacc[mt2][2 * kt + 1][0], sacc[mt2][2 * kt + 1][1], ph[mt2][2], pl[mt2][2]);
            split2(sacc[mt2][2 * kt + 1][2], sacc[mt2][2 * kt + 1][3], ph[mt2][3], pl[mt2][3]);
        }
        #pragma unroll
        for (int np = 0; np < 2; np++) {
            u32 bh[4], bl[4];
            u32 vd = sb32 + (OFF_VH + (u32)((kt * 16 + aRow) * 68 + h * 16 + np * 8) + aK) * 4u;
            LDSM4T(bh, vd);
            LDSM4T(bl, vd + 4352u * 4u);
            #pragma unroll
            for (int mt2 = 0; mt2 < 2; mt2++)
                #pragma unroll
                for (int ntl = 0; ntl < 2; ntl++) {
                    int nn = np * 2 + ntl;
                    mma16816(oacc[mt2][nn], ph[mt2], bh + ntl * 2);
                    mma16816(oacc[mt2][nn], ph[mt2], bl + ntl * 2);
                    mma16816(oacc[mt2][nn], pl[mt2], bh + ntl * 2);
                }
        }
    }
    // O epilogue -> QH/QL region (warp-local block: rows r0.., cols 32h..)
    #pragma unroll
    for (int mt2 = 0; mt2 < 2; mt2++)
        #pragma unroll
        for (int nn = 0; nn < 4; nn++) {
            int row0 = r0 + mt2 * 16 + g;
            u32 du = (u32)(h * 16 + nn * 4 + t);
            float ra = rinv[mt2][0], rb = rinv[mt2][1];
            u32 h0, l0, h1, l1;
            split2(oacc[mt2][nn][0] * ra, oacc[mt2][nn][1] * ra, h0, l0);
            split2(oacc[mt2][nn][2] * rb, oacc[mt2][nn][3] * rb, h1, l1);
            su[OFF_QH + (u32)(row0 * 68) + du]         = h0;
            su[OFF_QL + (u32)(row0 * 68) + du]         = l0;
            su[OFF_QH + (u32)((row0 + 8) * 68) + du]   = h1;
            su[OFF_QL + (u32)((row0 + 8) * 68) + du]   = l1;
        }

    // ---- proj: chunks 6,7 (chunk 6 already in flight) ----
    for (int c = 6; c < 8; c++) {
        CPWAIT0();
        __syncthreads();
        if (c == 6) cp_chunk(sb32, 7, 1, tid);

        float acc[4][4];
        #pragma unroll
        for (int n = 0; n < 4; n++)
            #pragma unroll
            for (int j = 0; j < 4; j++) acc[n][j] = 0.f;

        const u32 wb = OFF_W + (u32)(c & 1) * 8704u;
        #pragma unroll
        for (int ks = 0; ks < 8; ks++) {
            u32 ah2[4], al2[4];
            u32 ad = sb32 + (OFF_QH + (u32)((mt * 16 + aRow) * 68 + ks * 8) + aK) * 4u;
            LDSM4(ah2, ad);
            LDSM4(al2, ad + 4352u * 4u);
            #pragma unroll
            for (int np = 0; np < 2; np++) {
                u32 bh[4], bl[4];
                u32 bd = sb32 + (wb + (u32)((nh * 32 + np * 16 + bN) * 68 + ks * 8) + bK) * 4u;
                LDSM4(bh, bd);
                LDSM4(bl, bd + 4352u * 4u);
                #pragma unroll
                for (int ntl = 0; ntl < 2; ntl++) {
                    int nt = np * 2 + ntl;
                    mma16816(acc[nt], ah2, bh + ntl * 2);
                    mma16816(acc[nt], ah2, bl + ntl * 2);
                    mma16816(acc[nt], al2, bh + ntl * 2);
                }
            }
        }
        float* og = out + (size_t)b * 8192;
        #pragma unroll
        for (int nt = 0; nt < 4; nt++) {
            int col = (c - 6) * 64 + nh * 32 + nt * 8 + 2 * t;
            float b0 = sbf[384 + col], b1 = sbf[384 + col + 1];
            int rw = mt * 16 + g;
            *(float2*)&og[rw * 128 + col]       = make_float2(acc[nt][0] + b0, acc[nt][1] + b1);
            *(float2*)&og[(rw + 8) * 128 + col] = make_float2(acc[nt][2] + b0, acc[nt][3] + b1);
        }
    }
}

extern "C" void kernel_launch(void* const* d_in, const int* in_sizes, int n_in,
                              void* d_out, int out_size) {
    const float* x          = (const float*)d_in[0];
    const float* mask       = (const float*)d_in[1];
    const float* qkv_w      = (const float*)d_in[2];
    const float* qkv_b      = (const float*)d_in[3];
    const float* proj_w     = (const float*)d_in[4];
    const float* proj_b     = (const float*)d_in[5];
    const float* bias_table = (const float*)d_in[6];
    const int*   rel_index  = (const int*)d_in[7];
    float* out = (float*)d_out;

    wprep_kernel<<<64, 256>>>(qkv_w, proj_w);
    bias_prep_kernel<<<32, 256>>>(bias_table, rel_index);

    cudaFuncSetAttribute(win_attn6,
                         cudaFuncAttributeMaxDynamicSharedMemorySize, SMEM_BYTES);
    win_attn6<<<16384, 256, SMEM_BYTES>>>(x, mask, qkv_b, proj_b, out);
}